// round 9
// baseline (speedup 1.0000x reference)
#include <cuda_runtime.h>
#include <cuda_fp16.h>
#include <math.h>

#define NN 50000
#define EE 800000
#define EP (EE + NN)
#define NB ((NN + 1023) / 1024)
#define GEMM_BLKS 782                 // 2 n-tiles x 391 m-tiles of 128x128
#define CNT_BLKS  3321                // ceil(EP/256)

// ---------------- scratch (device globals; zero-initialized at load) --------
__device__ int    g_cnt[NN];          // re-zeroed by k_scan every launch
__device__ int    g_bsum[64];
__device__ int    g_done;             // scan rendezvous (self-resetting)
__device__ int    g_done2;
__device__ int    g_off[NN + 1];
__device__ int    g_woff[NN + 1];
__device__ int    g_srcs[EP];
__device__ __half g_h1h[(size_t)NN * 256];
__device__ float  g_as1[NN * 8];
__device__ float  g_ad1[NN * 8];
__device__ float  g_h2[NN * 16];
__device__ float  g_as2[NN];
__device__ float  g_ad2[NN];
__device__ float  g_h3[NN * 16];      // stores h3 * dinv (premultiplied)
__device__ float  g_dinv[NN];

__device__ __forceinline__ float leaky(float x) { return x > 0.f ? x : 0.2f * x; }

__device__ __forceinline__ unsigned long long pack2(float lo, float hi) {
    unsigned long long r;
    asm("mov.b64 %0, {%1, %2};" : "=l"(r) : "f"(lo), "f"(hi));
    return r;
}
__device__ __forceinline__ void unpack2(unsigned long long v, float& lo, float& hi) {
    asm("mov.b64 {%0, %1}, %2;" : "=f"(lo), "=f"(hi) : "l"(v));
}
__device__ __forceinline__ void ffma2(unsigned long long& acc, unsigned long long a,
                                      unsigned long long b) {
    asm("fma.rn.f32x2 %0, %1, %2, %0;" : "+l"(acc) : "l"(a), "l"(b));
}

// ---------------- K1: GEMM1 (+alpha1 in epilogue) || CSR count --------------
__global__ void __launch_bounds__(256) k_fused1(const float* __restrict__ A,
                                                const float* __restrict__ B,
                                                const int* __restrict__ ei,
                                                const float* __restrict__ a_s,
                                                const float* __restrict__ a_d) {
    if (blockIdx.x >= GEMM_BLKS) {
        int i = (blockIdx.x - GEMM_BLKS) * 256 + threadIdx.x;
        if (i < EP) {
            int d = (i < EE) ? ei[EE + i] : (i - EE);
            atomicAdd(&g_cnt[d], 1);
        }
        return;
    }

    __shared__ float As[8 * 128];
    __shared__ float Bs[8 * 128];
    const int M = NN;
    int tid = threadIdx.x;
    int bn = (blockIdx.x & 1) * 128;
    int bm = (blockIdx.x >> 1) * 128;
    int tr = tid >> 4, tc = tid & 15;
    unsigned long long acc2[8][4];
#pragma unroll
    for (int m = 0; m < 8; m++)
#pragma unroll
        for (int n = 0; n < 4; n++) acc2[m][n] = 0ull;

    for (int k0 = 0; k0 < 128; k0 += 8) {
        {
            int r = tid >> 1, q = (tid & 1) * 4;
            int gr = bm + r;
            float4 av = make_float4(0.f, 0.f, 0.f, 0.f);
            if (gr < M) av = *(const float4*)(A + (size_t)gr * 128 + k0 + q);
            As[(q + 0) * 128 + r] = av.x; As[(q + 1) * 128 + r] = av.y;
            As[(q + 2) * 128 + r] = av.z; As[(q + 3) * 128 + r] = av.w;
        }
        {
            int kk = tid >> 5, c4 = (tid & 31) * 4;
            float4 bv = *(const float4*)(B + (size_t)(k0 + kk) * 256 + bn + c4);
            *(float4*)&Bs[kk * 128 + c4] = bv;
        }
        __syncthreads();
#pragma unroll
        for (int kk = 0; kk < 8; kk++) {
            float a[8], b[8];
            *(float4*)(a)     = *(const float4*)&As[kk * 128 + tr * 8];
            *(float4*)(a + 4) = *(const float4*)&As[kk * 128 + tr * 8 + 4];
            *(float4*)(b)     = *(const float4*)&Bs[kk * 128 + tc * 8];
            *(float4*)(b + 4) = *(const float4*)&Bs[kk * 128 + tc * 8 + 4];
            unsigned long long bp[4];
#pragma unroll
            for (int n = 0; n < 4; n++) bp[n] = pack2(b[2 * n], b[2 * n + 1]);
#pragma unroll
            for (int m = 0; m < 8; m++) {
                unsigned long long ap = pack2(a[m], a[m]);
#pragma unroll
                for (int n = 0; n < 4; n++) ffma2(acc2[m][n], ap, bp[n]);
            }
        }
        __syncthreads();
    }

    float asv[8], adv[8];
    *(float4*)(asv)     = *(const float4*)(a_s + bn + tc * 8);
    *(float4*)(asv + 4) = *(const float4*)(a_s + bn + tc * 8 + 4);
    *(float4*)(adv)     = *(const float4*)(a_d + bn + tc * 8);
    *(float4*)(adv + 4) = *(const float4*)(a_d + bn + tc * 8 + 4);

#pragma unroll
    for (int m = 0; m < 8; m++) {
        int gr = bm + tr * 8 + m;
        float f[8];
#pragma unroll
        for (int n = 0; n < 4; n++) unpack2(acc2[m][n], f[2 * n], f[2 * n + 1]);
        if (gr < M) {
            __half hv[8];
#pragma unroll
            for (int j = 0; j < 8; j++) hv[j] = __float2half_rn(f[j]);
            *(uint4*)(g_h1h + (size_t)gr * 256 + bn + tc * 8) = *(uint4*)hv;
        }
        float s = 0.f, d = 0.f;
#pragma unroll
        for (int j = 0; j < 8; j++) { s += f[j] * asv[j]; d += f[j] * adv[j]; }
        s += __shfl_xor_sync(0xffffffffu, s, 1);
        s += __shfl_xor_sync(0xffffffffu, s, 2);
        d += __shfl_xor_sync(0xffffffffu, d, 1);
        d += __shfl_xor_sync(0xffffffffu, d, 2);
        if ((tc & 3) == 0 && gr < M) {
            int hd = (bn >> 5) + (tc >> 2);
            g_as1[gr * 8 + hd] = s;
            g_ad1[gr * 8 + hd] = d;
        }
    }
}

// ---------------- K2: single-pass device-wide scan + offsets + dinv ---------
__global__ void __launch_bounds__(1024) k_scan() {
    __shared__ int buf[1024];
    __shared__ int pre;
    int b = blockIdx.x, t = threadIdx.x;
    int i = b * 1024 + t;
    int v = (i < NN) ? g_cnt[i] : 0;
    buf[t] = v;
    __syncthreads();
#pragma unroll
    for (int ofs = 1; ofs < 1024; ofs <<= 1) {
        int x = (t >= ofs) ? buf[t - ofs] : 0;
        __syncthreads();
        buf[t] += x;
        __syncthreads();
    }
    int incl = buf[t];
    int total = buf[1023];

    if (t == 0) {
        g_bsum[b] = total;
        __threadfence();
        atomicAdd(&g_done, 1);
        while (*(volatile int*)&g_done < NB) { }
        int acc = 0;
        for (int j = 0; j < b; j++) acc += g_bsum[j];
        pre = acc;
    }
    __syncthreads();

    int e = pre + incl - v;
    if (i < NN) {
        g_off[i] = e;
        g_woff[i] = e;
        g_dinv[i] = rsqrtf((float)v);
        g_cnt[i] = 0;
    }
    if (b == NB - 1 && t == 1023) {
        g_off[NN] = pre + total;
        g_woff[NN] = pre + total;
    }
    if (t == 0) {
        int d2 = atomicAdd(&g_done2, 1);
        if (d2 == NB - 1) { g_done = 0; g_done2 = 0; }
    }
}

__global__ void k_scatter(const int* __restrict__ ei) {
    int i = blockIdx.x * blockDim.x + threadIdx.x;
    if (i >= EP) return;
    int s, d;
    if (i < EE) { s = ei[i]; d = ei[EE + i]; }
    else        { s = i - EE; d = s; }
    int pos = atomicAdd(&g_woff[d], 1);
    g_srcs[pos] = s;
}

// ---------------- GAT1: single-pass softmax-aggregation (scale-invariant) ---
// out[w,h,:] = (sum_e ew * h1[s,h,:]) / (sum_e ew),  ew = exp(leaky(as+ad))
// Prefetched index/logit gathers; fused ELU + GEMM2 + alpha2 epilogue.
__global__ void __launch_bounds__(256) k_gat1(const float* __restrict__ b1,
                                              const float* __restrict__ W2,
                                              const float* __restrict__ a2s,
                                              const float* __restrict__ a2d) {
    __shared__ float Ws[16 * 256];  // W2 transposed
    for (int i = threadIdx.x; i < 4096; i += 256) {
        int c = i >> 8, f = i & 255;
        Ws[i] = W2[f * 16 + c];
    }
    __syncthreads();

    int w = (blockIdx.x * blockDim.x + threadIdx.x) >> 5;
    if (w >= NN) return;
    int lane = threadIdx.x & 31;
    int beg = g_off[w], end = g_off[w + 1];

    int hl = lane & 7;           // head this lane computes weights for
    int jg = lane >> 3;          // edge sub-slot 0..3
    int hh = lane >> 2;          // head owning features [lane*8, lane*8+8)
    float adv_l = g_ad1[w * 8 + hl];

    // prefetch group 0
    int sa, sb; float asa, asb;
    {
        int ea = beg + jg;     if (ea >= end) ea = end - 1;
        int eb = beg + 4 + jg; if (eb >= end) eb = end - 1;
        sa = g_srcs[ea]; sb = g_srcs[eb];
        asa = g_as1[sa * 8 + hl]; asb = g_as1[sb * 8 + hl];
    }

    float smv = 0.f;
    float4 acc0 = make_float4(0.f, 0.f, 0.f, 0.f);
    float4 acc1 = make_float4(0.f, 0.f, 0.f, 0.f);

    for (int e0 = beg; e0 < end; e0 += 8) {
        // prefetch next group (clamped => always-safe loads)
        int nsa, nsb; float nasa, nasb;
        {
            int ea = e0 + 8 + jg;      if (ea >= end) ea = end - 1;
            int eb = e0 + 12 + jg;     if (eb >= end) eb = end - 1;
            nsa = g_srcs[ea]; nsb = g_srcs[eb];
            nasa = g_as1[nsa * 8 + hl]; nasb = g_as1[nsb * 8 + hl];
        }

        float ewa = __expf(leaky(asa + adv_l));
        float ewb = __expf(leaky(asb + adv_l));
        if (e0 + jg     >= end) ewa = 0.f;   // validity folded into weight
        if (e0 + 4 + jg >= end) ewb = 0.f;
        smv += ewa + ewb;

#pragma unroll
        for (int j = 0; j < 8; j++) {
            float wk = (j < 4) ? __shfl_sync(0xffffffffu, ewa, j * 8 + hh)
                               : __shfl_sync(0xffffffffu, ewb, (j - 4) * 8 + hh);
            int   s  = (j < 4) ? __shfl_sync(0xffffffffu, sa, j * 8)
                               : __shfl_sync(0xffffffffu, sb, (j - 4) * 8);
            uint4 v = *((const uint4*)(g_h1h + (size_t)s * 256) + lane);
            float2 f0 = __half22float2(*(__half2*)&v.x);
            float2 f1 = __half22float2(*(__half2*)&v.y);
            float2 f2 = __half22float2(*(__half2*)&v.z);
            float2 f3 = __half22float2(*(__half2*)&v.w);
            acc0.x += f0.x * wk; acc0.y += f0.y * wk;
            acc0.z += f1.x * wk; acc0.w += f1.y * wk;
            acc1.x += f2.x * wk; acc1.y += f2.y * wk;
            acc1.z += f3.x * wk; acc1.w += f3.y * wk;
        }
        sa = nsa; sb = nsb; asa = nasa; asb = nasb;
    }

    // per-head denominator: combine the 4 jg stripes holding the same head
    smv += __shfl_xor_sync(0xffffffffu, smv, 8);
    smv += __shfl_xor_sync(0xffffffffu, smv, 16);
    float di_l = 1.0f / smv;                       // lane's head hl
    float di_h = __shfl_sync(0xffffffffu, di_l, hh);  // head owning our features

    // epilogue: normalize, + b1, ELU, fused GEMM2 (x W2 [256,16]) + alpha2
    float r[8];
    const float* bb = b1 + lane * 8;
    r[0] = acc0.x * di_h + bb[0]; r[1] = acc0.y * di_h + bb[1];
    r[2] = acc0.z * di_h + bb[2]; r[3] = acc0.w * di_h + bb[3];
    r[4] = acc1.x * di_h + bb[4]; r[5] = acc1.y * di_h + bb[5];
    r[6] = acc1.z * di_h + bb[6]; r[7] = acc1.w * di_h + bb[7];
#pragma unroll
    for (int j = 0; j < 8; j++) r[j] = r[j] > 0.f ? r[j] : expm1f(r[j]);

    float p[16];
#pragma unroll
    for (int c = 0; c < 16; c++) {
        const float4* wt = (const float4*)(Ws + c * 256 + lane * 8);
        float4 w0 = wt[0], w1 = wt[1];
        p[c] = r[0] * w0.x + r[1] * w0.y + r[2] * w0.z + r[3] * w0.w +
               r[4] * w1.x + r[5] * w1.y + r[6] * w1.z + r[7] * w1.w;
    }
#pragma unroll
    for (int c = 0; c < 16; c++)
#pragma unroll
        for (int o = 16; o; o >>= 1)
            p[c] += __shfl_xor_sync(0xffffffffu, p[c], o);

    if (lane == 0) {
        float4* o4 = (float4*)(g_h2 + (size_t)w * 16);
        o4[0] = make_float4(p[0], p[1], p[2], p[3]);
        o4[1] = make_float4(p[4], p[5], p[6], p[7]);
        o4[2] = make_float4(p[8], p[9], p[10], p[11]);
        o4[3] = make_float4(p[12], p[13], p[14], p[15]);
        float s2 = 0.f, d2 = 0.f;
#pragma unroll
        for (int c = 0; c < 16; c++) {
            s2 += p[c] * __ldg(a2s + c);
            d2 += p[c] * __ldg(a2d + c);
        }
        g_as2[w] = s2;
        g_ad2[w] = d2;
    }
}

// ---------------- GAT2: single-pass + fused ELU + GCN GEMM ------------------
// lanes 0-7 compute the 8 edge-exps per group; unnormalized accumulate.
__global__ void __launch_bounds__(256) k_gat2(const float* __restrict__ b2,
                                              const float* __restrict__ W3) {
    __shared__ float w3s[256];
    if (threadIdx.x < 256) w3s[threadIdx.x] = W3[threadIdx.x];
    __syncthreads();

    int w = (blockIdx.x * blockDim.x + threadIdx.x) >> 5;
    if (w >= NN) return;
    int lane = threadIdx.x & 31;
    int beg = g_off[w], end = g_off[w + 1];
    float ad2d = g_ad2[w];
    int c = lane & 15, half = lane >> 4;
    int l8 = lane & 7;

    // prefetch group 0
    int s8; float a8;
    {
        int e = beg + l8; if (e >= end) e = end - 1;
        s8 = g_srcs[e];
        a8 = g_as2[s8];
    }

    float smv = 0.f, acc = 0.f;
    for (int e0 = beg; e0 < end; e0 += 8) {
        int ns8; float na8;
        {
            int e = e0 + 8 + l8; if (e >= end) e = end - 1;
            ns8 = g_srcs[e];
            na8 = g_as2[ns8];
        }
        float ew = __expf(leaky(a8 + ad2d));
        if (e0 + l8 >= end) ew = 0.f;
        if (lane < 8) smv += ew;
#pragma unroll
        for (int q = 0; q < 4; q++) {
            int j = q * 2 + half;
            float wv = __shfl_sync(0xffffffffu, ew, j);
            int   s  = __shfl_sync(0xffffffffu, s8, j);
            acc += g_h2[(size_t)s * 16 + c] * wv;   // wv=0 if edge invalid
        }
        s8 = ns8; a8 = na8;
    }
#pragma unroll
    for (int o = 16; o; o >>= 1)
        smv += __shfl_xor_sync(0xffffffffu, smv, o);
    acc += __shfl_xor_sync(0xffffffffu, acc, 16);
    acc /= smv;

    float ov = acc + __ldg(b2 + c);
    float e2 = ov > 0.f ? ov : expm1f(ov);

    float h3 = 0.f;
#pragma unroll
    for (int k = 0; k < 16; k++) {
        float xk = __shfl_sync(0xffffffffu, e2, k);
        h3 += xk * w3s[k * 16 + c];
    }
    if (lane < 16) g_h3[(size_t)w * 16 + c] = h3 * g_dinv[w];
}

// ---------------- GCN aggregation (h3 premultiplied by dinv[src]) -----------
__global__ void __launch_bounds__(256) k_gcn(const float* __restrict__ b3,
                                             float* __restrict__ out) {
    int w = (blockIdx.x * blockDim.x + threadIdx.x) >> 5;
    if (w >= NN) return;
    int lane = threadIdx.x & 31;
    int beg = g_off[w], end = g_off[w + 1];
    float did = g_dinv[w];
    int c = lane & 15, half = lane >> 4;
    float acc = 0.f;
    for (int e0 = beg; e0 < end; e0 += 8) {
#pragma unroll
        for (int q = 0; q < 4; q++) {
            int e = e0 + q * 2 + half;
            int ec = (e < end) ? e : (end - 1);
            int s = g_srcs[ec];
            float v = g_h3[(size_t)s * 16 + c];
            if (e < end) acc += v;
        }
    }
    acc += __shfl_xor_sync(0xffffffffu, acc, 16);
    if (lane < 16) out[(size_t)w * 16 + c] = acc * did + __ldg(b3 + c);
}

// ---------------- launch ----------------------------------------------------
extern "C" void kernel_launch(void* const* d_in, const int* in_sizes, int n_in,
                              void* d_out, int out_size) {
    const float* x      = (const float*)d_in[0];
    const int*   ei     = (const int*)  d_in[1];
    const float* W1     = (const float*)d_in[2];
    const float* a_src1 = (const float*)d_in[3];
    const float* a_dst1 = (const float*)d_in[4];
    const float* b1     = (const float*)d_in[5];
    const float* W2     = (const float*)d_in[6];
    const float* a_src2 = (const float*)d_in[7];
    const float* a_dst2 = (const float*)d_in[8];
    const float* b2     = (const float*)d_in[9];
    const float* W3     = (const float*)d_in[10];
    const float* b3     = (const float*)d_in[11];
    float* out = (float*)d_out;

    k_fused1 <<<GEMM_BLKS + CNT_BLKS, 256>>>(x, W1, ei, a_src1, a_dst1);
    k_scan   <<<NB, 1024>>>();
    k_scatter<<<(EP + 255) / 256, 256>>>(ei);
    k_gat1   <<<(NN + 7) / 8, 256>>>(b1, W2, a_src2, a_dst2);   // profile slot 4
    k_gat2   <<<(NN + 7) / 8, 256>>>(b2, W3);
    k_gcn    <<<(NN + 7) / 8, 256>>>(b3, out);
}

// round 10
// speedup vs baseline: 1.4930x; 1.4930x over previous
#include <cuda_runtime.h>
#include <cuda_fp16.h>
#include <math.h>

#define NN 50000
#define EE 800000
#define EP (EE + NN)
#define NB ((NN + 1023) / 1024)
#define GEMM_BLKS 782                 // 2 n-tiles x 391 m-tiles of 128x128
#define CNT_BLKS  3321                // ceil(EP/256)

// ---------------- scratch (device globals; zero-initialized at load) --------
__device__ int    g_cnt[NN];          // re-zeroed by k_scan every launch
__device__ int    g_bsum[64];
__device__ int    g_done;             // scan rendezvous (self-resetting)
__device__ int    g_done2;
__device__ int    g_off[NN + 1];
__device__ int    g_woff[NN + 1];
__device__ int    g_srcs[EP];
__device__ __half g_h1h[(size_t)NN * 256];
__device__ float  g_ew[(size_t)EP * 8];   // GAT1 edge weights; reused by GAT2
__device__ float  g_as1[NN * 8];
__device__ float  g_ad1[NN * 8];
__device__ float  g_h2[NN * 16];
__device__ float  g_as2[NN];
__device__ float  g_ad2[NN];
__device__ float  g_h3[NN * 16];      // stores h3 * dinv (premultiplied)
__device__ float  g_dinv[NN];

__device__ __forceinline__ float leaky(float x) { return x > 0.f ? x : 0.2f * x; }

__device__ __forceinline__ float sel8(const float* a, int h) {
    float v = a[0];
#pragma unroll
    for (int i = 1; i < 8; i++) if (h == i) v = a[i];
    return v;
}

__device__ __forceinline__ unsigned long long pack2(float lo, float hi) {
    unsigned long long r;
    asm("mov.b64 %0, {%1, %2};" : "=l"(r) : "f"(lo), "f"(hi));
    return r;
}
__device__ __forceinline__ void unpack2(unsigned long long v, float& lo, float& hi) {
    asm("mov.b64 {%0, %1}, %2;" : "=f"(lo), "=f"(hi) : "l"(v));
}
__device__ __forceinline__ void ffma2(unsigned long long& acc, unsigned long long a,
                                      unsigned long long b) {
    asm("fma.rn.f32x2 %0, %1, %2, %0;" : "+l"(acc) : "l"(a), "l"(b));
}

// ---------------- K1: GEMM1 (+alpha1 in epilogue) || CSR count --------------
__global__ void __launch_bounds__(256) k_fused1(const float* __restrict__ A,
                                                const float* __restrict__ B,
                                                const int* __restrict__ ei,
                                                const float* __restrict__ a_s,
                                                const float* __restrict__ a_d) {
    if (blockIdx.x >= GEMM_BLKS) {
        int i = (blockIdx.x - GEMM_BLKS) * 256 + threadIdx.x;
        if (i < EP) {
            int d = (i < EE) ? ei[EE + i] : (i - EE);
            atomicAdd(&g_cnt[d], 1);
        }
        return;
    }

    __shared__ float As[8 * 128];
    __shared__ float Bs[8 * 128];
    const int M = NN;
    int tid = threadIdx.x;
    int bn = (blockIdx.x & 1) * 128;
    int bm = (blockIdx.x >> 1) * 128;
    int tr = tid >> 4, tc = tid & 15;
    unsigned long long acc2[8][4];
#pragma unroll
    for (int m = 0; m < 8; m++)
#pragma unroll
        for (int n = 0; n < 4; n++) acc2[m][n] = 0ull;

    for (int k0 = 0; k0 < 128; k0 += 8) {
        {
            int r = tid >> 1, q = (tid & 1) * 4;
            int gr = bm + r;
            float4 av = make_float4(0.f, 0.f, 0.f, 0.f);
            if (gr < M) av = *(const float4*)(A + (size_t)gr * 128 + k0 + q);
            As[(q + 0) * 128 + r] = av.x; As[(q + 1) * 128 + r] = av.y;
            As[(q + 2) * 128 + r] = av.z; As[(q + 3) * 128 + r] = av.w;
        }
        {
            int kk = tid >> 5, c4 = (tid & 31) * 4;
            float4 bv = *(const float4*)(B + (size_t)(k0 + kk) * 256 + bn + c4);
            *(float4*)&Bs[kk * 128 + c4] = bv;
        }
        __syncthreads();
#pragma unroll
        for (int kk = 0; kk < 8; kk++) {
            float a[8], b[8];
            *(float4*)(a)     = *(const float4*)&As[kk * 128 + tr * 8];
            *(float4*)(a + 4) = *(const float4*)&As[kk * 128 + tr * 8 + 4];
            *(float4*)(b)     = *(const float4*)&Bs[kk * 128 + tc * 8];
            *(float4*)(b + 4) = *(const float4*)&Bs[kk * 128 + tc * 8 + 4];
            unsigned long long bp[4];
#pragma unroll
            for (int n = 0; n < 4; n++) bp[n] = pack2(b[2 * n], b[2 * n + 1]);
#pragma unroll
            for (int m = 0; m < 8; m++) {
                unsigned long long ap = pack2(a[m], a[m]);
#pragma unroll
                for (int n = 0; n < 4; n++) ffma2(acc2[m][n], ap, bp[n]);
            }
        }
        __syncthreads();
    }

    float asv[8], adv[8];
    *(float4*)(asv)     = *(const float4*)(a_s + bn + tc * 8);
    *(float4*)(asv + 4) = *(const float4*)(a_s + bn + tc * 8 + 4);
    *(float4*)(adv)     = *(const float4*)(a_d + bn + tc * 8);
    *(float4*)(adv + 4) = *(const float4*)(a_d + bn + tc * 8 + 4);

#pragma unroll
    for (int m = 0; m < 8; m++) {
        int gr = bm + tr * 8 + m;
        float f[8];
#pragma unroll
        for (int n = 0; n < 4; n++) unpack2(acc2[m][n], f[2 * n], f[2 * n + 1]);
        if (gr < M) {
            __half hv[8];
#pragma unroll
            for (int j = 0; j < 8; j++) hv[j] = __float2half_rn(f[j]);
            *(uint4*)(g_h1h + (size_t)gr * 256 + bn + tc * 8) = *(uint4*)hv;
        }
        float s = 0.f, d = 0.f;
#pragma unroll
        for (int j = 0; j < 8; j++) { s += f[j] * asv[j]; d += f[j] * adv[j]; }
        s += __shfl_xor_sync(0xffffffffu, s, 1);
        s += __shfl_xor_sync(0xffffffffu, s, 2);
        d += __shfl_xor_sync(0xffffffffu, d, 1);
        d += __shfl_xor_sync(0xffffffffu, d, 2);
        if ((tc & 3) == 0 && gr < M) {
            int hd = (bn >> 5) + (tc >> 2);
            g_as1[gr * 8 + hd] = s;
            g_ad1[gr * 8 + hd] = d;
        }
    }
}

// ---------------- K2: single-pass device-wide scan + offsets + dinv ---------
__global__ void __launch_bounds__(1024) k_scan() {
    __shared__ int buf[1024];
    __shared__ int pre;
    int b = blockIdx.x, t = threadIdx.x;
    int i = b * 1024 + t;
    int v = (i < NN) ? g_cnt[i] : 0;
    buf[t] = v;
    __syncthreads();
#pragma unroll
    for (int ofs = 1; ofs < 1024; ofs <<= 1) {
        int x = (t >= ofs) ? buf[t - ofs] : 0;
        __syncthreads();
        buf[t] += x;
        __syncthreads();
    }
    int incl = buf[t];
    int total = buf[1023];

    if (t == 0) {
        g_bsum[b] = total;
        __threadfence();
        atomicAdd(&g_done, 1);
        while (*(volatile int*)&g_done < NB) { }
        int acc = 0;
        for (int j = 0; j < b; j++) acc += g_bsum[j];
        pre = acc;
    }
    __syncthreads();

    int e = pre + incl - v;
    if (i < NN) {
        g_off[i] = e;
        g_woff[i] = e;
        g_dinv[i] = rsqrtf((float)v);
        g_cnt[i] = 0;
    }
    if (b == NB - 1 && t == 1023) {
        g_off[NN] = pre + total;
        g_woff[NN] = pre + total;
    }
    if (t == 0) {
        int d2 = atomicAdd(&g_done2, 1);
        if (d2 == NB - 1) { g_done = 0; g_done2 = 0; }
    }
}

__global__ void k_scatter(const int* __restrict__ ei) {
    int i = blockIdx.x * blockDim.x + threadIdx.x;
    if (i >= EP) return;
    int s, d;
    if (i < EE) { s = ei[i]; d = ei[EE + i]; }
    else        { s = i - EE; d = s; }
    int pos = atomicAdd(&g_woff[d], 1);
    g_srcs[pos] = s;
}

// ---------------- GAT1 (R8 two-pass structure) + occupancy + prefetch -------
__global__ void __launch_bounds__(256, 5) k_gat1(const float* __restrict__ b1,
                                                 const float* __restrict__ W2,
                                                 const float* __restrict__ a2s,
                                                 const float* __restrict__ a2d) {
    __shared__ float Ws[16 * 256];  // W2 transposed
    for (int i = threadIdx.x; i < 4096; i += 256) {
        int c = i >> 8, f = i & 255;
        Ws[i] = W2[f * 16 + c];
    }
    __syncthreads();

    int w = (blockIdx.x * blockDim.x + threadIdx.x) >> 5;
    if (w >= NN) return;
    int lane = threadIdx.x & 31;
    int beg = g_off[w], end = g_off[w + 1];

    float adv[8];
    {
        const float4* p = (const float4*)(g_ad1 + w * 8);
        float4 x0 = p[0], x1 = p[1];
        adv[0] = x0.x; adv[1] = x0.y; adv[2] = x0.z; adv[3] = x0.w;
        adv[4] = x1.x; adv[5] = x1.y; adv[6] = x1.z; adv[7] = x1.w;
    }

    // pass 1: exp weights cached coalesced + sums
    float sm[8];
#pragma unroll
    for (int k = 0; k < 8; k++) sm[k] = 0.f;
    for (int e = beg + lane; e < end; e += 32) {
        int s = g_srcs[e];
        const float4* p = (const float4*)(g_as1 + s * 8);
        float4 x0 = p[0], x1 = p[1];
        float as[8] = {x0.x, x0.y, x0.z, x0.w, x1.x, x1.y, x1.z, x1.w};
        float ew[8];
#pragma unroll
        for (int k = 0; k < 8; k++) {
            ew[k] = __expf(leaky(as[k] + adv[k]));
            sm[k] += ew[k];
        }
        float4* q = (float4*)(g_ew + (size_t)e * 8);
        q[0] = make_float4(ew[0], ew[1], ew[2], ew[3]);
        q[1] = make_float4(ew[4], ew[5], ew[6], ew[7]);
    }
    __syncwarp();
#pragma unroll
    for (int k = 0; k < 8; k++)
#pragma unroll
        for (int o = 16; o; o >>= 1)
            sm[k] += __shfl_xor_sync(0xffffffffu, sm[k], o);
    float di[8];
#pragma unroll
    for (int k = 0; k < 8; k++) di[k] = 1.0f / sm[k];

    // pass 2: 8 edges/group, branch-free, software-pipelined index/weight loads
    int hl = lane & 7;
    int jg = lane >> 3;
    int hh = lane >> 2;
    float di_l = sel8(di, hl);
    float4 acc0 = make_float4(0.f, 0.f, 0.f, 0.f);
    float4 acc1 = make_float4(0.f, 0.f, 0.f, 0.f);

    // prefetch group 0
    int sa, sb; float wa, wb;
    {
        int ea = beg + jg;     if (ea >= end) ea = end - 1;
        int eb = beg + 4 + jg; if (eb >= end) eb = end - 1;
        sa = g_srcs[ea]; sb = g_srcs[eb];
        wa = g_ew[(size_t)ea * 8 + hl] * di_l;
        wb = g_ew[(size_t)eb * 8 + hl] * di_l;
    }

    for (int e0 = beg; e0 < end; e0 += 8) {
        // prefetch next group (clamped => always-safe loads)
        int nsa, nsb; float nwa, nwb;
        {
            int ea = e0 + 8 + jg;  if (ea >= end) ea = end - 1;
            int eb = e0 + 12 + jg; if (eb >= end) eb = end - 1;
            nsa = g_srcs[ea]; nsb = g_srcs[eb];
            nwa = g_ew[(size_t)ea * 8 + hl] * di_l;
            nwb = g_ew[(size_t)eb * 8 + hl] * di_l;
        }
#pragma unroll
        for (int j = 0; j < 8; j++) {
            float wk = (j < 4) ? __shfl_sync(0xffffffffu, wa, j * 8 + hh)
                               : __shfl_sync(0xffffffffu, wb, (j - 4) * 8 + hh);
            int   s  = (j < 4) ? __shfl_sync(0xffffffffu, sa, j * 8)
                               : __shfl_sync(0xffffffffu, sb, (j - 4) * 8);
            if (e0 + j >= end) wk = 0.f;          // predicate, not branch
            uint4 v = *((const uint4*)(g_h1h + (size_t)s * 256) + lane);
            float2 f0 = __half22float2(*(__half2*)&v.x);
            float2 f1 = __half22float2(*(__half2*)&v.y);
            float2 f2 = __half22float2(*(__half2*)&v.z);
            float2 f3 = __half22float2(*(__half2*)&v.w);
            acc0.x += f0.x * wk; acc0.y += f0.y * wk;
            acc0.z += f1.x * wk; acc0.w += f1.y * wk;
            acc1.x += f2.x * wk; acc1.y += f2.y * wk;
            acc1.z += f3.x * wk; acc1.w += f3.y * wk;
        }
        sa = nsa; sb = nsb; wa = nwa; wb = nwb;
    }

    // epilogue: + b1, ELU, fused GEMM2 (x W2 [256,16]) + alpha2
    float r[8];
    const float* bb = b1 + lane * 8;
    r[0] = acc0.x + bb[0]; r[1] = acc0.y + bb[1];
    r[2] = acc0.z + bb[2]; r[3] = acc0.w + bb[3];
    r[4] = acc1.x + bb[4]; r[5] = acc1.y + bb[5];
    r[6] = acc1.z + bb[6]; r[7] = acc1.w + bb[7];
#pragma unroll
    for (int j = 0; j < 8; j++) r[j] = r[j] > 0.f ? r[j] : expm1f(r[j]);

    float p[16];
#pragma unroll
    for (int c = 0; c < 16; c++) {
        const float4* wt = (const float4*)(Ws + c * 256 + lane * 8);
        float4 w0 = wt[0], w1 = wt[1];
        p[c] = r[0] * w0.x + r[1] * w0.y + r[2] * w0.z + r[3] * w0.w +
               r[4] * w1.x + r[5] * w1.y + r[6] * w1.z + r[7] * w1.w;
    }
#pragma unroll
    for (int c = 0; c < 16; c++)
#pragma unroll
        for (int o = 16; o; o >>= 1)
            p[c] += __shfl_xor_sync(0xffffffffu, p[c], o);

    if (lane == 0) {
        float4* o4 = (float4*)(g_h2 + (size_t)w * 16);
        o4[0] = make_float4(p[0], p[1], p[2], p[3]);
        o4[1] = make_float4(p[4], p[5], p[6], p[7]);
        o4[2] = make_float4(p[8], p[9], p[10], p[11]);
        o4[3] = make_float4(p[12], p[13], p[14], p[15]);
        float s2 = 0.f, d2 = 0.f;
#pragma unroll
        for (int c = 0; c < 16; c++) {
            s2 += p[c] * __ldg(a2s + c);
            d2 += p[c] * __ldg(a2d + c);
        }
        g_as2[w] = s2;
        g_ad2[w] = d2;
    }
}

// ---------------- GAT2 (R8 version) + fused ELU + GCN GEMM ------------------
__global__ void __launch_bounds__(256) k_gat2(const float* __restrict__ b2,
                                              const float* __restrict__ W3) {
    __shared__ float w3s[256];
    if (threadIdx.x < 256) w3s[threadIdx.x] = W3[threadIdx.x];
    __syncthreads();

    int w = (blockIdx.x * blockDim.x + threadIdx.x) >> 5;
    if (w >= NN) return;
    int lane = threadIdx.x & 31;
    int beg = g_off[w], end = g_off[w + 1];
    float ad2d = g_ad2[w];

    float smv = 0.f;
    for (int e = beg + lane; e < end; e += 32) {
        float ev = __expf(leaky(g_as2[g_srcs[e]] + ad2d));
        g_ew[e] = ev;
        smv += ev;
    }
    __syncwarp();
#pragma unroll
    for (int o = 16; o; o >>= 1)
        smv += __shfl_xor_sync(0xffffffffu, smv, o);
    float divd = 1.0f / smv;

    int c = lane & 15, half = lane >> 4;
    float acc = 0.f;
    for (int e0 = beg; e0 < end; e0 += 8) {
#pragma unroll
        for (int q = 0; q < 4; q++) {
            int e = e0 + q * 2 + half;
            int ec = (e < end) ? e : (end - 1);
            int s = g_srcs[ec];
            float wv = g_ew[ec];
            float v = g_h2[(size_t)s * 16 + c];
            if (e < end) acc += v * wv;
        }
    }
    acc += __shfl_xor_sync(0xffffffffu, acc, 16);
    acc *= divd;

    float ov = acc + __ldg(b2 + c);
    float e2 = ov > 0.f ? ov : expm1f(ov);

    float h3 = 0.f;
#pragma unroll
    for (int k = 0; k < 16; k++) {
        float xk = __shfl_sync(0xffffffffu, e2, k);
        h3 += xk * w3s[k * 16 + c];
    }
    if (lane < 16) g_h3[(size_t)w * 16 + c] = h3 * g_dinv[w];
}

// ---------------- GCN aggregation (h3 premultiplied by dinv[src]) -----------
__global__ void __launch_bounds__(256) k_gcn(const float* __restrict__ b3,
                                             float* __restrict__ out) {
    int w = (blockIdx.x * blockDim.x + threadIdx.x) >> 5;
    if (w >= NN) return;
    int lane = threadIdx.x & 31;
    int beg = g_off[w], end = g_off[w + 1];
    float did = g_dinv[w];
    int c = lane & 15, half = lane >> 4;
    float acc = 0.f;
    for (int e0 = beg; e0 < end; e0 += 8) {
#pragma unroll
        for (int q = 0; q < 4; q++) {
            int e = e0 + q * 2 + half;
            int ec = (e < end) ? e : (end - 1);
            int s = g_srcs[ec];
            float v = g_h3[(size_t)s * 16 + c];
            if (e < end) acc += v;
        }
    }
    acc += __shfl_xor_sync(0xffffffffu, acc, 16);
    if (lane < 16) out[(size_t)w * 16 + c] = acc * did + __ldg(b3 + c);
}

// ---------------- launch ----------------------------------------------------
extern "C" void kernel_launch(void* const* d_in, const int* in_sizes, int n_in,
                              void* d_out, int out_size) {
    const float* x      = (const float*)d_in[0];
    const int*   ei     = (const int*)  d_in[1];
    const float* W1     = (const float*)d_in[2];
    const float* a_src1 = (const float*)d_in[3];
    const float* a_dst1 = (const float*)d_in[4];
    const float* b1     = (const float*)d_in[5];
    const float* W2     = (const float*)d_in[6];
    const float* a_src2 = (const float*)d_in[7];
    const float* a_dst2 = (const float*)d_in[8];
    const float* b2     = (const float*)d_in[9];
    const float* W3     = (const float*)d_in[10];
    const float* b3     = (const float*)d_in[11];
    float* out = (float*)d_out;

    k_fused1 <<<GEMM_BLKS + CNT_BLKS, 256>>>(x, W1, ei, a_src1, a_dst1);
    k_scan   <<<NB, 1024>>>();
    k_scatter<<<(EP + 255) / 256, 256>>>(ei);
    k_gat1   <<<(NN + 7) / 8, 256>>>(b1, W2, a_src2, a_dst2);   // profile slot 4
    k_gat2   <<<(NN + 7) / 8, 256>>>(b2, W3);
    k_gcn    <<<(NN + 7) / 8, 256>>>(b3, out);
}

// round 11
// speedup vs baseline: 1.5101x; 1.0114x over previous
#include <cuda_runtime.h>
#include <cuda_fp16.h>
#include <math.h>

#define NN 50000
#define EE 800000
#define EP (EE + NN)
#define NB ((NN + 1023) / 1024)
#define GEMM_BLKS 782                 // 2 n-tiles x 391 m-tiles of 128x128
#define CNT_BLKS  3321                // ceil(EP/256)

// ---------------- scratch (device globals; zero-initialized at load) --------
__device__ int    g_cnt[NN];          // re-zeroed by k_scan every launch
__device__ int    g_bsum[64];
__device__ int    g_done;             // scan rendezvous (self-resetting)
__device__ int    g_done2;
__device__ int    g_off[NN + 1];
__device__ int    g_woff[NN + 1];
__device__ __align__(16) int    g_srcs[EP];
__device__ __align__(16) __half g_h1h[(size_t)NN * 256];
__device__ __align__(16) float  g_ew[(size_t)EP * 8];  // GAT1 weights; reused by GAT2
__device__ float  g_as1[NN * 8];
__device__ float  g_ad1[NN * 8];
__device__ float  g_h2[NN * 16];
__device__ float  g_as2[NN];
__device__ float  g_ad2[NN];
__device__ float  g_h3[NN * 16];      // stores h3 * dinv (premultiplied)
__device__ float  g_dinv[NN];

__device__ __forceinline__ float leaky(float x) { return x > 0.f ? x : 0.2f * x; }

__device__ __forceinline__ float sel8(const float* a, int h) {
    float v = a[0];
#pragma unroll
    for (int i = 1; i < 8; i++) if (h == i) v = a[i];
    return v;
}

__device__ __forceinline__ unsigned long long pack2(float lo, float hi) {
    unsigned long long r;
    asm("mov.b64 %0, {%1, %2};" : "=l"(r) : "f"(lo), "f"(hi));
    return r;
}
__device__ __forceinline__ void unpack2(unsigned long long v, float& lo, float& hi) {
    asm("mov.b64 {%0, %1}, %2;" : "=f"(lo), "=f"(hi) : "l"(v));
}
__device__ __forceinline__ void ffma2(unsigned long long& acc, unsigned long long a,
                                      unsigned long long b) {
    asm("fma.rn.f32x2 %0, %1, %2, %0;" : "+l"(acc) : "l"(a), "l"(b));
}

// ---------------- K1: GEMM1 (+alpha1 in epilogue) || CSR count --------------
__global__ void __launch_bounds__(256) k_fused1(const float* __restrict__ A,
                                                const float* __restrict__ B,
                                                const int* __restrict__ ei,
                                                const float* __restrict__ a_s,
                                                const float* __restrict__ a_d) {
    if (blockIdx.x >= GEMM_BLKS) {
        int i = (blockIdx.x - GEMM_BLKS) * 256 + threadIdx.x;
        if (i < EP) {
            int d = (i < EE) ? ei[EE + i] : (i - EE);
            atomicAdd(&g_cnt[d], 1);
        }
        return;
    }

    __shared__ float As[8 * 128];
    __shared__ float Bs[8 * 128];
    const int M = NN;
    int tid = threadIdx.x;
    int bn = (blockIdx.x & 1) * 128;
    int bm = (blockIdx.x >> 1) * 128;
    int tr = tid >> 4, tc = tid & 15;
    unsigned long long acc2[8][4];
#pragma unroll
    for (int m = 0; m < 8; m++)
#pragma unroll
        for (int n = 0; n < 4; n++) acc2[m][n] = 0ull;

    for (int k0 = 0; k0 < 128; k0 += 8) {
        {
            int r = tid >> 1, q = (tid & 1) * 4;
            int gr = bm + r;
            float4 av = make_float4(0.f, 0.f, 0.f, 0.f);
            if (gr < M) av = *(const float4*)(A + (size_t)gr * 128 + k0 + q);
            As[(q + 0) * 128 + r] = av.x; As[(q + 1) * 128 + r] = av.y;
            As[(q + 2) * 128 + r] = av.z; As[(q + 3) * 128 + r] = av.w;
        }
        {
            int kk = tid >> 5, c4 = (tid & 31) * 4;
            float4 bv = *(const float4*)(B + (size_t)(k0 + kk) * 256 + bn + c4);
            *(float4*)&Bs[kk * 128 + c4] = bv;
        }
        __syncthreads();
#pragma unroll
        for (int kk = 0; kk < 8; kk++) {
            float a[8], b[8];
            *(float4*)(a)     = *(const float4*)&As[kk * 128 + tr * 8];
            *(float4*)(a + 4) = *(const float4*)&As[kk * 128 + tr * 8 + 4];
            *(float4*)(b)     = *(const float4*)&Bs[kk * 128 + tc * 8];
            *(float4*)(b + 4) = *(const float4*)&Bs[kk * 128 + tc * 8 + 4];
            unsigned long long bp[4];
#pragma unroll
            for (int n = 0; n < 4; n++) bp[n] = pack2(b[2 * n], b[2 * n + 1]);
#pragma unroll
            for (int m = 0; m < 8; m++) {
                unsigned long long ap = pack2(a[m], a[m]);
#pragma unroll
                for (int n = 0; n < 4; n++) ffma2(acc2[m][n], ap, bp[n]);
            }
        }
        __syncthreads();
    }

    float asv[8], adv[8];
    *(float4*)(asv)     = *(const float4*)(a_s + bn + tc * 8);
    *(float4*)(asv + 4) = *(const float4*)(a_s + bn + tc * 8 + 4);
    *(float4*)(adv)     = *(const float4*)(a_d + bn + tc * 8);
    *(float4*)(adv + 4) = *(const float4*)(a_d + bn + tc * 8 + 4);

#pragma unroll
    for (int m = 0; m < 8; m++) {
        int gr = bm + tr * 8 + m;
        float f[8];
#pragma unroll
        for (int n = 0; n < 4; n++) unpack2(acc2[m][n], f[2 * n], f[2 * n + 1]);
        if (gr < M) {
            __half hv[8];
#pragma unroll
            for (int j = 0; j < 8; j++) hv[j] = __float2half_rn(f[j]);
            *(uint4*)(g_h1h + (size_t)gr * 256 + bn + tc * 8) = *(uint4*)hv;
        }
        float s = 0.f, d = 0.f;
#pragma unroll
        for (int j = 0; j < 8; j++) { s += f[j] * asv[j]; d += f[j] * adv[j]; }
        s += __shfl_xor_sync(0xffffffffu, s, 1);
        s += __shfl_xor_sync(0xffffffffu, s, 2);
        d += __shfl_xor_sync(0xffffffffu, d, 1);
        d += __shfl_xor_sync(0xffffffffu, d, 2);
        if ((tc & 3) == 0 && gr < M) {
            int hd = (bn >> 5) + (tc >> 2);
            g_as1[gr * 8 + hd] = s;
            g_ad1[gr * 8 + hd] = d;
        }
    }
}

// ---------------- K2: single-pass device-wide scan + offsets + dinv ---------
__global__ void __launch_bounds__(1024) k_scan() {
    __shared__ int buf[1024];
    __shared__ int pre;
    int b = blockIdx.x, t = threadIdx.x;
    int i = b * 1024 + t;
    int v = (i < NN) ? g_cnt[i] : 0;
    buf[t] = v;
    __syncthreads();
#pragma unroll
    for (int ofs = 1; ofs < 1024; ofs <<= 1) {
        int x = (t >= ofs) ? buf[t - ofs] : 0;
        __syncthreads();
        buf[t] += x;
        __syncthreads();
    }
    int incl = buf[t];
    int total = buf[1023];

    if (t == 0) {
        g_bsum[b] = total;
        __threadfence();
        atomicAdd(&g_done, 1);
        while (*(volatile int*)&g_done < NB) { }
        int acc = 0;
        for (int j = 0; j < b; j++) acc += g_bsum[j];
        pre = acc;
    }
    __syncthreads();

    int e = pre + incl - v;
    if (i < NN) {
        g_off[i] = e;
        g_woff[i] = e;
        g_dinv[i] = rsqrtf((float)v);
        g_cnt[i] = 0;
    }
    if (b == NB - 1 && t == 1023) {
        g_off[NN] = pre + total;
        g_woff[NN] = pre + total;
    }
    if (t == 0) {
        int d2 = atomicAdd(&g_done2, 1);
        if (d2 == NB - 1) { g_done = 0; g_done2 = 0; }
    }
}

__global__ void k_scatter(const int* __restrict__ ei) {
    int i = blockIdx.x * blockDim.x + threadIdx.x;
    if (i >= EP) return;
    int s, d;
    if (i < EE) { s = ei[i]; d = ei[EE + i]; }
    else        { s = i - EE; d = s; }
    int pos = atomicAdd(&g_woff[d], 1);
    g_srcs[pos] = s;
}

// ---------------- GAT1: two-pass; pass2 = aligned int4 srcs + direct ew -----
__global__ void __launch_bounds__(256, 5) k_gat1(const float* __restrict__ b1,
                                                 const float* __restrict__ W2,
                                                 const float* __restrict__ a2s,
                                                 const float* __restrict__ a2d) {
    __shared__ float Ws[16 * 256];  // W2 transposed
    for (int i = threadIdx.x; i < 4096; i += 256) {
        int c = i >> 8, f = i & 255;
        Ws[i] = W2[f * 16 + c];
    }
    __syncthreads();

    int w = (blockIdx.x * blockDim.x + threadIdx.x) >> 5;
    if (w >= NN) return;
    int lane = threadIdx.x & 31;
    int beg = g_off[w], end = g_off[w + 1];

    float adv[8];
    {
        const float4* p = (const float4*)(g_ad1 + w * 8);
        float4 x0 = p[0], x1 = p[1];
        adv[0] = x0.x; adv[1] = x0.y; adv[2] = x0.z; adv[3] = x0.w;
        adv[4] = x1.x; adv[5] = x1.y; adv[6] = x1.z; adv[7] = x1.w;
    }

    // pass 1: exp weights cached coalesced + sums (one edge per lane)
    float sm[8];
#pragma unroll
    for (int k = 0; k < 8; k++) sm[k] = 0.f;
    for (int e = beg + lane; e < end; e += 32) {
        int s = g_srcs[e];
        const float4* p = (const float4*)(g_as1 + s * 8);
        float4 x0 = p[0], x1 = p[1];
        float as[8] = {x0.x, x0.y, x0.z, x0.w, x1.x, x1.y, x1.z, x1.w};
        float ew[8];
#pragma unroll
        for (int k = 0; k < 8; k++) {
            ew[k] = __expf(leaky(as[k] + adv[k]));
            sm[k] += ew[k];
        }
        float4* q = (float4*)(g_ew + (size_t)e * 8);
        q[0] = make_float4(ew[0], ew[1], ew[2], ew[3]);
        q[1] = make_float4(ew[4], ew[5], ew[6], ew[7]);
    }
    __syncwarp();
#pragma unroll
    for (int k = 0; k < 8; k++)
#pragma unroll
        for (int o = 16; o; o >>= 1)
            sm[k] += __shfl_xor_sync(0xffffffffu, sm[k], o);
    float di[8];
#pragma unroll
    for (int k = 0; k < 8; k++) di[k] = 1.0f / sm[k];

    // pass 2: aligned groups of 4 edges, NO shfl, fp16 group-accumulate.
    int hh = lane >> 2;                  // head owning features [lane*8, +8)
    float di_h = sel8(di, hh);
    float fac[8];
#pragma unroll
    for (int j = 0; j < 8; j++) fac[j] = 0.f;

    int e0beg = beg & ~3;
    int elast = (end - 1) & ~3;
    int4 s4 = *(const int4*)(g_srcs + e0beg);
    for (int e0 = e0beg; e0 < end; e0 += 4) {
        int e1 = (e0 + 4 <= elast) ? (e0 + 4) : elast;   // clamped prefetch
        int4 ns4 = *(const int4*)(g_srcs + e1);

        float w0 = g_ew[(size_t)(e0 + 0) * 8 + hh];
        float w1 = g_ew[(size_t)(e0 + 1) * 8 + hh];
        float w2 = g_ew[(size_t)(e0 + 2) * 8 + hh];
        float w3 = g_ew[(size_t)(e0 + 3) * 8 + hh];

        uint4 m0 = *((const uint4*)(g_h1h + (size_t)s4.x * 256) + lane);
        uint4 m1 = *((const uint4*)(g_h1h + (size_t)s4.y * 256) + lane);
        uint4 m2 = *((const uint4*)(g_h1h + (size_t)s4.z * 256) + lane);
        uint4 m3 = *((const uint4*)(g_h1h + (size_t)s4.w * 256) + lane);

        w0 = (e0 >= beg)                   ? w0 * di_h : 0.f;
        w1 = (e0 + 1 >= beg && e0 + 1 < end) ? w1 * di_h : 0.f;
        w2 = (e0 + 2 >= beg && e0 + 2 < end) ? w2 * di_h : 0.f;
        w3 = (e0 + 3 >= beg && e0 + 3 < end) ? w3 * di_h : 0.f;
        __half2 wh0 = __float2half2_rn(w0);
        __half2 wh1 = __float2half2_rn(w1);
        __half2 wh2 = __float2half2_rn(w2);
        __half2 wh3 = __float2half2_rn(w3);

        __half2 a0 = __hmul2(*(__half2*)&m0.x, wh0);
        __half2 a1 = __hmul2(*(__half2*)&m0.y, wh0);
        __half2 a2 = __hmul2(*(__half2*)&m0.z, wh0);
        __half2 a3 = __hmul2(*(__half2*)&m0.w, wh0);
        a0 = __hfma2(*(__half2*)&m1.x, wh1, a0);
        a1 = __hfma2(*(__half2*)&m1.y, wh1, a1);
        a2 = __hfma2(*(__half2*)&m1.z, wh1, a2);
        a3 = __hfma2(*(__half2*)&m1.w, wh1, a3);
        a0 = __hfma2(*(__half2*)&m2.x, wh2, a0);
        a1 = __hfma2(*(__half2*)&m2.y, wh2, a1);
        a2 = __hfma2(*(__half2*)&m2.z, wh2, a2);
        a3 = __hfma2(*(__half2*)&m2.w, wh2, a3);
        a0 = __hfma2(*(__half2*)&m3.x, wh3, a0);
        a1 = __hfma2(*(__half2*)&m3.y, wh3, a1);
        a2 = __hfma2(*(__half2*)&m3.z, wh3, a2);
        a3 = __hfma2(*(__half2*)&m3.w, wh3, a3);

        float2 t;
        t = __half22float2(a0); fac[0] += t.x; fac[1] += t.y;
        t = __half22float2(a1); fac[2] += t.x; fac[3] += t.y;
        t = __half22float2(a2); fac[4] += t.x; fac[5] += t.y;
        t = __half22float2(a3); fac[6] += t.x; fac[7] += t.y;

        s4 = ns4;
    }

    // epilogue: + b1, ELU, fused GEMM2 (x W2 [256,16]) + alpha2
    float r[8];
    const float* bb = b1 + lane * 8;
#pragma unroll
    for (int j = 0; j < 8; j++) {
        float v = fac[j] + bb[j];
        r[j] = v > 0.f ? v : expm1f(v);
    }

    float p[16];
#pragma unroll
    for (int c = 0; c < 16; c++) {
        const float4* wt = (const float4*)(Ws + c * 256 + lane * 8);
        float4 w0 = wt[0], w1 = wt[1];
        p[c] = r[0] * w0.x + r[1] * w0.y + r[2] * w0.z + r[3] * w0.w +
               r[4] * w1.x + r[5] * w1.y + r[6] * w1.z + r[7] * w1.w;
    }
#pragma unroll
    for (int c = 0; c < 16; c++)
#pragma unroll
        for (int o = 16; o; o >>= 1)
            p[c] += __shfl_xor_sync(0xffffffffu, p[c], o);

    if (lane == 0) {
        float4* o4 = (float4*)(g_h2 + (size_t)w * 16);
        o4[0] = make_float4(p[0], p[1], p[2], p[3]);
        o4[1] = make_float4(p[4], p[5], p[6], p[7]);
        o4[2] = make_float4(p[8], p[9], p[10], p[11]);
        o4[3] = make_float4(p[12], p[13], p[14], p[15]);
        float s2 = 0.f, d2 = 0.f;
#pragma unroll
        for (int c = 0; c < 16; c++) {
            s2 += p[c] * __ldg(a2s + c);
            d2 += p[c] * __ldg(a2d + c);
        }
        g_as2[w] = s2;
        g_ad2[w] = d2;
    }
}

// ---------------- GAT2 + fused ELU + GCN GEMM -------------------------------
__global__ void __launch_bounds__(256) k_gat2(const float* __restrict__ b2,
                                              const float* __restrict__ W3) {
    __shared__ float w3s[256];
    if (threadIdx.x < 256) w3s[threadIdx.x] = W3[threadIdx.x];
    __syncthreads();

    int w = (blockIdx.x * blockDim.x + threadIdx.x) >> 5;
    if (w >= NN) return;
    int lane = threadIdx.x & 31;
    int beg = g_off[w], end = g_off[w + 1];
    float ad2d = g_ad2[w];

    float smv = 0.f;
    for (int e = beg + lane; e < end; e += 32) {
        float ev = __expf(leaky(g_as2[g_srcs[e]] + ad2d));
        g_ew[e] = ev;
        smv += ev;
    }
    __syncwarp();
#pragma unroll
    for (int o = 16; o; o >>= 1)
        smv += __shfl_xor_sync(0xffffffffu, smv, o);
    float divd = 1.0f / smv;

    int c = lane & 15, half = lane >> 4;
    float acc = 0.f;
    for (int e0 = beg; e0 < end; e0 += 8) {
#pragma unroll
        for (int q = 0; q < 4; q++) {
            int e = e0 + q * 2 + half;
            int ec = (e < end) ? e : (end - 1);
            int s = g_srcs[ec];
            float wv = g_ew[ec];
            float v = g_h2[(size_t)s * 16 + c];
            if (e < end) acc += v * wv;
        }
    }
    acc += __shfl_xor_sync(0xffffffffu, acc, 16);
    acc *= divd;

    float ov = acc + __ldg(b2 + c);
    float e2 = ov > 0.f ? ov : expm1f(ov);

    float h3 = 0.f;
#pragma unroll
    for (int k = 0; k < 16; k++) {
        float xk = __shfl_sync(0xffffffffu, e2, k);
        h3 += xk * w3s[k * 16 + c];
    }
    if (lane < 16) g_h3[(size_t)w * 16 + c] = h3 * g_dinv[w];
}

// ---------------- GCN aggregation (h3 premultiplied by dinv[src]) -----------
__global__ void __launch_bounds__(256) k_gcn(const float* __restrict__ b3,
                                             float* __restrict__ out) {
    int w = (blockIdx.x * blockDim.x + threadIdx.x) >> 5;
    if (w >= NN) return;
    int lane = threadIdx.x & 31;
    int beg = g_off[w], end = g_off[w + 1];
    float did = g_dinv[w];
    int c = lane & 15, half = lane >> 4;
    float acc = 0.f;
    for (int e0 = beg; e0 < end; e0 += 8) {
#pragma unroll
        for (int q = 0; q < 4; q++) {
            int e = e0 + q * 2 + half;
            int ec = (e < end) ? e : (end - 1);
            int s = g_srcs[ec];
            float v = g_h3[(size_t)s * 16 + c];
            if (e < end) acc += v;
        }
    }
    acc += __shfl_xor_sync(0xffffffffu, acc, 16);
    if (lane < 16) out[(size_t)w * 16 + c] = acc * did + __ldg(b3 + c);
}

// ---------------- launch ----------------------------------------------------
extern "C" void kernel_launch(void* const* d_in, const int* in_sizes, int n_in,
                              void* d_out, int out_size) {
    const float* x      = (const float*)d_in[0];
    const int*   ei     = (const int*)  d_in[1];
    const float* W1     = (const float*)d_in[2];
    const float* a_src1 = (const float*)d_in[3];
    const float* a_dst1 = (const float*)d_in[4];
    const float* b1     = (const float*)d_in[5];
    const float* W2     = (const float*)d_in[6];
    const float* a_src2 = (const float*)d_in[7];
    const float* a_dst2 = (const float*)d_in[8];
    const float* b2     = (const float*)d_in[9];
    const float* W3     = (const float*)d_in[10];
    const float* b3     = (const float*)d_in[11];
    float* out = (float*)d_out;

    k_fused1 <<<GEMM_BLKS + CNT_BLKS, 256>>>(x, W1, ei, a_src1, a_dst1);
    k_scan   <<<NB, 1024>>>();
    k_scatter<<<(EP + 255) / 256, 256>>>(ei);
    k_gat1   <<<(NN + 7) / 8, 256>>>(b1, W2, a_src2, a_dst2);   // profile slot 4
    k_gat2   <<<(NN + 7) / 8, 256>>>(b2, W3);
    k_gcn    <<<(NN + 7) / 8, 256>>>(b3, out);
}